// round 2
// baseline (speedup 1.0000x reference)
#include <cuda_runtime.h>
#include <math.h>

#define GRP 64
#define MN  128
#define NNODES (GRP*MN)
#define NRAD 16

__device__ __forceinline__ float rcp_approx(float x) {
    float r;
    asm("rcp.approx.f32 %0, %1;" : "=f"(r) : "f"(x));
    return r;
}

__global__ __launch_bounds__(MN, 16)
void rsaef_kernel(const float* __restrict__ sf,   // (N,4)
                  const float* __restrict__ pos,  // (N,3)
                  float* __restrict__ out)        // features (N,64) then si (N,64)
{
    __shared__ float4 sh_pq[MN];  // pos.xyz, q
    __shared__ float4 sh_mu[MN];  // mu = sf[:, {3,1,2}]

    const int g  = blockIdx.x;
    const int k  = blockIdx.y;   // radial index 0..15
    const int i  = threadIdx.x;
    const int node = g * MN + i;

    // cooperative load of this group's nodes into smem
    {
        const float* p = pos + (size_t)g * MN * 3;
        const float* f = sf  + (size_t)g * MN * 4;
        float4 pq;
        pq.x = p[i*3+0]; pq.y = p[i*3+1]; pq.z = p[i*3+2];
        pq.w = f[i*4+0];
        sh_pq[i] = pq;
        float4 mu;
        mu.x = f[i*4+3]; mu.y = f[i*4+1]; mu.z = f[i*4+2]; mu.w = 0.f;
        sh_mu[i] = mu;
    }
    __syncthreads();

    // per-thread radial constants in double (matches numpy f64 -> f32 cast)
    const double PI  = 3.14159265358979323846;
    const double KCd = 14.399645351950548;
    float wv, halfinvw, ginv, inv2w2, l0f, l1w;
    {
        double sig = 0.5 + (double)k * (2.5 / 15.0);
        double w   = sqrt((1.0 + sig*sig) * 0.5);
        double pi15 = pow(PI, 1.5);
        double s3 = sig*sig*sig;
        double s5 = s3*sig*sig;
        double cl0rec  = 1.0 / sqrt(pi15 * s3);
        double cl0mult = 1.0 / (pow(2.0*PI, 1.5) * s3);
        double cl1rec  = 1.0 / sqrt(pi15 * s5 * 3.0 / 2.0);
        double L0F = cl0rec / cl0mult;
        double L1W = sqrt(3.0) * sig * sig * cl1rec / cl0mult;
        const double INV_SQRT_PI_D = 0.5641895835477562869480794515607725858;
        wv       = (float)w;
        halfinvw = (float)(0.5 / w);
        ginv     = (float)(INV_SQRT_PI_D / w);       // 1/(w*sqrt(pi))
        inv2w2   = (float)(1.0 / (2.0 * w * w));
        l0f      = (float)(KCd * L0F);
        l1w      = (float)(KCd * L1W);
    }

    const float4 me = sh_pq[i];

    float acc0 = 0.f, a1x = 0.f, a1y = 0.f, a1z = 0.f;

    #pragma unroll 4
    for (int j = 0; j < MN; j++) {
        float4 pj  = sh_pq[j];
        float4 muj = sh_mu[j];
        float mask = (j == i) ? 0.f : 1.f;
        float qj = pj.w * mask;
        float mx = muj.x * mask, my = muj.y * mask, mz = muj.z * mask;

        float Rx = me.x - pj.x, Ry = me.y - pj.y, Rz = me.z - pj.z;
        float r2 = fmaf(Rx, Rx, fmaf(Ry, Ry, Rz*Rz));
        r2 = fmaxf(r2, 1e-20f);
        float inv_r = rsqrtf(r2);
        float r     = r2 * inv_r;
        float hx = Rx * inv_r, hy = Ry * inv_r, hz = Rz * inv_r;
        float muR = fmaf(mx, hx, fmaf(my, hy, mz * hz));

        // radial kernel
        float u  = r * halfinvw;
        float e  = __expf(-u * u);           // 2 mul + MUFU.EX2
        // branchless erf: Abramowitz–Stegun 7.1.26, |err| <= 1.5e-7, reuses e
        float d  = fmaf(0.3275911f, u, 1.0f);
        float t  = rcp_approx(d);
        float P  = fmaf(1.061405429f, t, -1.453152027f);
        P = fmaf(P, t, 1.421413741f);
        P = fmaf(P, t, -0.284496736f);
        P = fmaf(P, t, 0.254829592f);
        float erfu = fmaf(-(P * t), e, 1.0f);

        float gg   = e * ginv;
        float T    = erfu * inv_r;
        float fp   = (gg - T) * inv_r;
        float fpor = fp * inv_r;
        // fpp = -gg*inv2w2 - 2*fpor  =>  fpor - fpp = 3*fpor + gg*inv2w2
        float coef = muR * fmaf(gg, inv2w2, 3.0f * fpor);
        float A    = fmaf(fp, qj, coef);

        acc0 = fmaf(qj, T, fmaf(-muR, fp, acc0));
        a1x  = fmaf(A, hx, fmaf(-fpor, mx, a1x));
        a1y  = fmaf(A, hy, fmaf(-fpor, my, a1y));
        a1z  = fmaf(A, hz, fmaf(-fpor, mz, a1z));
    }

    // features row: [l0 (16)] [l1 (16 x 3), component perm (1,2,0)]
    float* frow = out + (size_t)node * 64;
    frow[k]            = l0f * acc0;
    frow[16 + 3*k + 0] = l1w * a1y;   // component 1
    frow[16 + 3*k + 1] = l1w * a1z;   // component 2
    frow[16 + 3*k + 2] = l1w * a1x;   // component 0

    // self-interaction terms
    float* srow = out + (size_t)NNODES * 64 + (size_t)node * 64;
    const float* f = sf + (size_t)node * 4;
    float q = f[0], m1 = f[1], m2 = f[2], m3 = f[3];
    const float INV_SQRT_PI = 0.56418958354775628695f;
    float si0 = l0f * q * (2.0f * halfinvw) * INV_SQRT_PI;
    float w3  = wv * wv * wv;
    float sic = l1w * (1.f / (6.f * w3)) * INV_SQRT_PI;
    srow[k]            = si0;
    srow[16 + 3*k + 0] = sic * m1;
    srow[16 + 3*k + 1] = sic * m2;
    srow[16 + 3*k + 2] = sic * m3;
}

extern "C" void kernel_launch(void* const* d_in, const int* in_sizes, int n_in,
                              void* d_out, int out_size)
{
    const float* sf  = (const float*)d_in[0];  // source_feats (N,4)
    const float* pos = (const float*)d_in[1];  // node_positions (N,3)
    float* out = (float*)d_out;

    dim3 grid(GRP, NRAD);
    rsaef_kernel<<<grid, MN>>>(sf, pos, out);
}